// round 12
// baseline (speedup 1.0000x reference)
#include <cuda_runtime.h>
#include <cuda_bf16.h>
#include <cuda_fp16.h>
#include <math.h>

// Problem constants
constexpr int BN = 4;
constexpr int NF = 64;
constexpr int H  = 128;
constexpr int W  = 128;
constexpr int HW = H * W;
constexpr int K  = 9;

// Scratch (device globals: no runtime allocation allowed)
__device__ unsigned g_bufA[BN * NF * HW];           // packed (bf16 hi | lo<<16)
__device__ unsigned g_bufB[BN * NF * HW];
__device__ __align__(16) __half g_xt[BN * HW * NF]; // channel-last fp16 nbr for DCN gather
__device__ __nv_bfloat16 g_A1[2 * 9 * 2 * 64 * 72]; // conv1 mma weights (hi/lo, pad72)
__device__ __nv_bfloat16 g_A2[1 * 9 * 2 * 64 * 72];
__device__ __nv_bfloat16 g_A3[1 * 9 * 2 * 64 * 72];
__device__ __nv_bfloat16 g_Ao[9 * 2 * 32 * 72];     // offset-head weights [tap][var][m32][72]
__device__ __nv_bfloat16 g_Ad[9 * 2 * 64 * 72];     // DCN weights [ch=k][var][oc][c pad72]

__device__ __forceinline__ float lrelu(float v) { return v >= 0.f ? v : 0.1f * v; }

__device__ __forceinline__ unsigned pack_hl(float v) {
    const __nv_bfloat16 h = __float2bfloat16(v);
    const __nv_bfloat16 l = __float2bfloat16(v - __bfloat162float(h));
    return (unsigned)__bfloat16_as_ushort(h) | ((unsigned)__bfloat16_as_ushort(l) << 16);
}

// Fragment-order B address within one px row (256 data bytes, stride 320):
//   block j = (klocal&7)>>1 holds {hi(2j,2j+1), hi(2j+8,2j+9), lo(2j,2j+1), lo(2j+8,2j+9)}
//   elem (ci): base + (ci>>4)*64 + ((ci&7)>>1)*16 + ((ci>>3)&1)*4 + (ci&1)*2; lo at +8.
__device__ __forceinline__ int bfrag_off(int ci) {
    return ((ci >> 4) << 6) + (((ci & 7) >> 1) << 4) + (((ci >> 3) & 1) << 2) + ((ci & 1) << 1);
}

// ---- mma.sync helpers ------------------------------------------------------
__device__ __forceinline__ unsigned smem_u32(const void* p) {
    unsigned a;
    asm("{ .reg .u64 t; cvta.to.shared.u64 t, %1; cvt.u32.u64 %0, t; }" : "=r"(a) : "l"(p));
    return a;
}
__device__ __forceinline__ void ldsm4(unsigned* a, unsigned saddr) {
    asm volatile("ldmatrix.sync.aligned.m8n8.x4.shared.b16 {%0,%1,%2,%3}, [%4];"
                 : "=r"(a[0]), "=r"(a[1]), "=r"(a[2]), "=r"(a[3]) : "r"(saddr));
}
__device__ __forceinline__ void mma16816(float* c, const unsigned* a, unsigned b0, unsigned b1) {
    asm volatile(
        "mma.sync.aligned.m16n8k16.row.col.f32.bf16.bf16.f32 "
        "{%0,%1,%2,%3}, {%4,%5,%6,%7}, {%8,%9}, {%0,%1,%2,%3};"
        : "+f"(c[0]), "+f"(c[1]), "+f"(c[2]), "+f"(c[3])
        : "r"(a[0]), "r"(a[1]), "r"(a[2]), "r"(a[3]), "r"(b0), "r"(b1));
}

// ---------------------------------------------------------------------------
// Merged weight prep (single launch, block-range dispatch).
// ---------------------------------------------------------------------------
__device__ __forceinline__ __nv_bfloat16 split_val(float wv, int var) {
    const __nv_bfloat16 h = __float2bfloat16(wv);
    return var ? __float2bfloat16(wv - __bfloat162float(h)) : h;
}

template <int CC>
__device__ __forceinline__ void prep_conv_w_elem(int i, const float* __restrict__ w,
                                                 __nv_bfloat16* __restrict__ A) {
    constexpr int CI = CC * 64;
    const int k   = i & 63;
    const int m   = (i >> 6) & 63;
    const int bt  = i >> 12;
    const int var = bt & 1;
    const int ct  = bt >> 1;            // cc*9 + tap
    const int tap = ct % 9;
    const int cc  = ct / 9;
    const float wv = w[((size_t)m * CI + cc * 64 + k) * 9 + tap];
    A[(size_t)ct * 9216 + var * 4608 + m * 72 + k] = split_val(wv, var);
}

__global__ void prep_weights(const float* __restrict__ w1, __nv_bfloat16* __restrict__ A1,
                             const float* __restrict__ w2, __nv_bfloat16* __restrict__ A2,
                             const float* __restrict__ w3, __nv_bfloat16* __restrict__ A3,
                             const float* __restrict__ wo, __nv_bfloat16* __restrict__ Ao,
                             const float* __restrict__ wd, __nv_bfloat16* __restrict__ Ad)
{
    const int blk = blockIdx.x;
    const int t   = threadIdx.x;
    if (blk < 576) {
        prep_conv_w_elem<2>(blk * 256 + t, w1, A1);
    } else if (blk < 864) {
        prep_conv_w_elem<1>((blk - 576) * 256 + t, w2, A2);
    } else if (blk < 1152) {
        prep_conv_w_elem<1>((blk - 864) * 256 + t, w3, A3);
    } else if (blk < 1296) {
        const int i = (blk - 1152) * 256 + t;
        const int k   = i & 63;
        const int m   = (i >> 6) & 31;
        const int var = (i >> 11) & 1;
        const int tap = i >> 12;
        float wv = 0.f;
        if (m < 27) wv = wo[((size_t)m * 64 + k) * 9 + tap];
        Ao[(size_t)(tap * 2 + var) * 2304 + m * 72 + k] = split_val(wv, var);
    } else {
        const int i = (blk - 1296) * 256 + t;
        const int c   = i & 63;
        const int oc  = (i >> 6) & 63;
        const int var = (i >> 12) & 1;
        const int ch  = i >> 13;
        const float wv = wd[(size_t)oc * 576 + c * 9 + ch];
        Ad[(size_t)ch * 9216 + var * 4608 + oc * 72 + c] = split_val(wv, var);
    }
}

// ---------------------------------------------------------------------------
// Channel-last fp16 transpose of nbr (row pad 72 halfs = 16B-aligned rows).
// ---------------------------------------------------------------------------
__global__ __launch_bounds__(256)
void prep_xt(const float* __restrict__ x, __half* __restrict__ xt)
{
    __shared__ __align__(16) __half tile[256 * 72];
    const int t    = threadIdx.x;
    const int pos0 = blockIdx.x * 256;
    const int b    = blockIdx.y;
    const float* xb = x + (size_t)b * NF * HW;
#pragma unroll 8
    for (int c = 0; c < 64; c++)
        tile[t * 72 + c] = __float2half(xb[(size_t)c * HW + pos0 + t]);
    __syncthreads();
    uint4* dst = (uint4*)(xt + ((size_t)b * HW + pos0) * 64);
    const uint4* srow = (const uint4*)(tile + t * 72);
#pragma unroll
    for (int j = 0; j < 8; j++) dst[t * 8 + j] = srow[j];
}

// ---------------------------------------------------------------------------
// HMMA conv3x3 + bias + leaky ReLU. Fragment-order B (hi/lo interleaved,
// px stride 320 -> one LDS.128 per b-frag). Single A buffer, 2 syncs/tap.
// Block 256 thr, tile 2 rows x 64 px x 64 oc. Grid (2, 64, B).
// ---------------------------------------------------------------------------
constexpr int BROW     = 66 * 320;                 // 21120 per row-plane
constexpr int A_OFF    = 4 * BROW;                 // 84480
constexpr int CSM_SIZE = A_OFF + 18432;            // 102912 -> 2 CTAs/SM

template <int CC, bool PACKED>
__global__ __launch_bounds__(256, 2)
void conv_mma_kernel(const float* __restrict__ fA, const float* __restrict__ fB,
                     const unsigned* __restrict__ pIn,
                     const __nv_bfloat16* __restrict__ Aw, const float* __restrict__ bias,
                     unsigned* __restrict__ out)
{
    extern __shared__ __align__(16) char smem[];
    const unsigned sbase = smem_u32(smem);
    const int t    = threadIdx.x;
    const int wid  = t >> 5;
    const int lane = t & 31;
    const int x0   = blockIdx.x * 64;
    const int y0   = blockIdx.y * 2;
    const int b    = blockIdx.z;

    const int ocg = wid & 1;
    const int pxg = wid >> 1;

    float acc[2][2][2][4];
#pragma unroll
    for (int r = 0; r < 2; r++)
#pragma unroll
        for (int mt = 0; mt < 2; mt++)
#pragma unroll
            for (int nt = 0; nt < 2; nt++)
#pragma unroll
                for (int c = 0; c < 4; c++) acc[r][mt][nt][c] = 0.f;

    for (int cc = 0; cc < CC; cc++) {
        if (cc) __syncthreads();                    // B planes free to overwrite
        // ---- stage B: 4 rows x 64 ci x 66 px (halo), fragment-order hi/lo
        for (int i = t; i < 4 * 64 * 66; i += 256) {
            const int pxi = i % 66;
            const int rci = i / 66;
            const int ci  = rci & 63;
            const int d   = rci >> 6;
            const int row = y0 + d - 1;
            const int xg  = x0 + pxi - 1;
            const bool ok = (row >= 0 && row < H && xg >= 0 && xg < W);
            unsigned pv = 0;
            if (PACKED) {
                if (ok) pv = pIn[((size_t)b * 64 + ci) * HW + row * W + xg];
            } else {
                float v = 0.f;
                if (ok) {
                    const float* src = cc ? fB : fA;
                    v = src[((size_t)b * 64 + ci) * HW + row * W + xg];
                }
                pv = pack_hl(v);
            }
            const int base = d * BROW + pxi * 320 + bfrag_off(ci);
            *(unsigned short*)(smem + base)     = (unsigned short)(pv & 0xFFFF);  // hi
            *(unsigned short*)(smem + base + 8) = (unsigned short)(pv >> 16);     // lo
        }

        for (int tap = 0; tap < 9; tap++) {
            const int g = cc * 9 + tap;
            __syncthreads();                        // B ready (tap0) / prior MMAs done
            {   // stage A[g] (single buffer, 18432 B)
                const uint4* srcw = (const uint4*)((const char*)Aw + (size_t)g * 18432);
                uint4* dst = (uint4*)(smem + A_OFF);
                for (int i = t; i < 1152; i += 256) dst[i] = srcw[i];
            }
            __syncthreads();                        // A ready

            const int dy = tap / 3, dx = tap - dy * 3;
#pragma unroll 1
            for (int ks = 0; ks < 4; ks++) {
                unsigned Ah[2][4], Al[2][4];
#pragma unroll
                for (int mt = 0; mt < 2; mt++) {
                    const unsigned ao = A_OFF +
                        ((ocg * 32 + mt * 16 + (lane & 15)) * 72 + ks * 16 + (lane >> 4) * 8) * 2;
                    ldsm4(Ah[mt], sbase + ao);
                    ldsm4(Al[mt], sbase + ao + 9216);
                }
#pragma unroll
                for (int r = 0; r < 2; r++) {
                    const char* Bp = smem + (r + dy) * BROW;
#pragma unroll
                    for (int nt = 0; nt < 2; nt++) {
                        const int pxi = pxg * 16 + nt * 8 + (lane >> 2) + dx;
                        const uint4 q = *(const uint4*)(Bp + pxi * 320 + ks * 64 + (lane & 3) * 16);
#pragma unroll
                        for (int mt = 0; mt < 2; mt++) {
                            mma16816(acc[r][mt][nt], Ah[mt], q.x, q.y);
                            mma16816(acc[r][mt][nt], Ah[mt], q.z, q.w);
                            mma16816(acc[r][mt][nt], Al[mt], q.x, q.y);
                        }
                    }
                }
            }
        }
    }

#pragma unroll
    for (int mt = 0; mt < 2; mt++) {
        const int ocA = ocg * 32 + mt * 16 + (lane >> 2);
        const int ocB = ocA + 8;
        const float bA = __ldg(bias + ocA);
        const float bB = __ldg(bias + ocB);
#pragma unroll
        for (int r = 0; r < 2; r++) {
            const int row = y0 + r;
#pragma unroll
            for (int nt = 0; nt < 2; nt++) {
                const int px = x0 + pxg * 16 + nt * 8 + 2 * (lane & 3);
                const float* c = acc[r][mt][nt];
                uint2 pA, pB;
                pA.x = pack_hl(lrelu(c[0] + bA)); pA.y = pack_hl(lrelu(c[1] + bA));
                pB.x = pack_hl(lrelu(c[2] + bB)); pB.y = pack_hl(lrelu(c[3] + bB));
                *(uint2*)(out + ((size_t)b * 64 + ocA) * HW + row * W + px) = pA;
                *(uint2*)(out + ((size_t)b * 64 + ocB) * HW + row * W + px) = pB;
            }
        }
    }
}

// ---------------------------------------------------------------------------
// HMMA offset/mask head: conv 64 -> 27(pad 32), fragment-order B.
// ---------------------------------------------------------------------------
constexpr int OSM_SIZE = A_OFF + 9216;             // 93696 -> 2 CTAs/SM

__global__ __launch_bounds__(256, 2)
void conv_off_mma_kernel(const unsigned* __restrict__ pIn, const __nv_bfloat16* __restrict__ Aw,
                         const float* __restrict__ bias,
                         float* __restrict__ off_out, float* __restrict__ mask_out)
{
    extern __shared__ __align__(16) char smem[];
    const unsigned sbase = smem_u32(smem);
    const int t    = threadIdx.x;
    const int wid  = t >> 5;
    const int lane = t & 31;
    const int x0   = blockIdx.x * 64;
    const int y0   = blockIdx.y * 2;
    const int b    = blockIdx.z;

    const int r   = wid & 1;
    const int pxg = wid >> 1;

    float acc[2][2][4];
#pragma unroll
    for (int mt = 0; mt < 2; mt++)
#pragma unroll
        for (int nt = 0; nt < 2; nt++)
#pragma unroll
            for (int c = 0; c < 4; c++) acc[mt][nt][c] = 0.f;

    for (int i = t; i < 4 * 64 * 66; i += 256) {
        const int pxi = i % 66;
        const int rci = i / 66;
        const int ci  = rci & 63;
        const int d   = rci >> 6;
        const int row = y0 + d - 1;
        const int xg  = x0 + pxi - 1;
        unsigned pv = 0;
        if (row >= 0 && row < H && xg >= 0 && xg < W)
            pv = pIn[((size_t)b * 64 + ci) * HW + row * W + xg];
        const int base = d * BROW + pxi * 320 + bfrag_off(ci);
        *(unsigned short*)(smem + base)     = (unsigned short)(pv & 0xFFFF);
        *(unsigned short*)(smem + base + 8) = (unsigned short)(pv >> 16);
    }

    for (int tap = 0; tap < 9; tap++) {
        __syncthreads();
        {
            const uint4* srcw = (const uint4*)((const char*)Aw + (size_t)tap * 9216);
            uint4* dst = (uint4*)(smem + A_OFF);
            for (int i = t; i < 576; i += 256) dst[i] = srcw[i];
        }
        __syncthreads();

        const int dy = tap / 3, dx = tap - dy * 3;
#pragma unroll 1
        for (int ks = 0; ks < 4; ks++) {
            unsigned Ah[2][4], Al[2][4];
#pragma unroll
            for (int mt = 0; mt < 2; mt++) {
                const unsigned ao = A_OFF +
                    ((mt * 16 + (lane & 15)) * 72 + ks * 16 + (lane >> 4) * 8) * 2;
                ldsm4(Ah[mt], sbase + ao);
                ldsm4(Al[mt], sbase + ao + 4608);
            }
            const char* Bp = smem + (r + dy) * BROW;
#pragma unroll
            for (int nt = 0; nt < 2; nt++) {
                const int pxi = pxg * 16 + nt * 8 + (lane >> 2) + dx;
                const uint4 q = *(const uint4*)(Bp + pxi * 320 + ks * 64 + (lane & 3) * 16);
#pragma unroll
                for (int mt = 0; mt < 2; mt++) {
                    mma16816(acc[mt][nt], Ah[mt], q.x, q.y);
                    mma16816(acc[mt][nt], Ah[mt], q.z, q.w);
                    mma16816(acc[mt][nt], Al[mt], q.x, q.y);
                }
            }
        }
    }

    const int row = y0 + r;
#pragma unroll
    for (int mt = 0; mt < 2; mt++) {
#pragma unroll
        for (int half = 0; half < 2; half++) {
            const int oc = mt * 16 + (lane >> 2) + half * 8;
            if (oc >= 27) continue;
            const float bb = __ldg(bias + oc);
#pragma unroll
            for (int nt = 0; nt < 2; nt++) {
                const int px = x0 + pxg * 16 + nt * 8 + 2 * (lane & 3);
                const float v0 = acc[mt][nt][2 * half]     + bb;
                const float v1 = acc[mt][nt][2 * half + 1] + bb;
                float2 v;
                if (oc < 18) {
                    v.x = 15.f * tanhf(v0);
                    v.y = 15.f * tanhf(v1);
                    *(float2*)(off_out + ((size_t)b * 18 + oc) * HW + row * W + px) = v;
                } else {
                    v.x = 1.f / (1.f + expf(-v0));
                    v.y = 1.f / (1.f + expf(-v1));
                    *(float2*)(mask_out + ((size_t)b * 9 + (oc - 18)) * HW + row * W + px) = v;
                }
            }
        }
    }
}

// ---------------------------------------------------------------------------
// DCNv2 + leaky ReLU, HMMA GEMM, channel-last fp16 gather, fragment-order B.
// Block 256 thr, tile 64 px x 64 oc. Grid (2, H, B).
// ---------------------------------------------------------------------------
constexpr int DW_OFF   = 9216;
constexpr int DB_OFF   = 18432;
constexpr int DA_OFF   = DB_OFF + 64 * 320;        // 38912
constexpr int DSM_SIZE = DA_OFF + 18432;           // 57344 -> 3 CTAs/SM

__global__ __launch_bounds__(256, 3)
void dcn_mma_kernel(const __half* __restrict__ xt, const float* __restrict__ offs,
                    const float* __restrict__ mask, const __nv_bfloat16* __restrict__ Ad,
                    const float* __restrict__ bias, float* __restrict__ out)
{
    extern __shared__ __align__(16) char smem[];
    int4*   sIdx4 = (int4*)smem;                     // [9][64]
    float4* sW4   = (float4*)(smem + DW_OFF);        // [9][64]
    const unsigned sbase = smem_u32(smem);

    const int t    = threadIdx.x;
    const int wid  = t >> 5;
    const int lane = t & 31;
    const int x0   = blockIdx.x * 64;
    const int y    = blockIdx.y;
    const int b    = blockIdx.z;

    for (int i = t; i < 64 * K; i += 256) {
        const int px = i & 63;
        const int k  = i >> 6;
        const int xx = x0 + px;
        const int base = y * W + xx;
        const float oy = offs[((size_t)b * 18 + 2 * k) * HW + base];
        const float ox = offs[((size_t)b * 18 + 2 * k + 1) * HW + base];
        const float m  = mask[((size_t)b * K + k) * HW + base];
        const float py  = (float)(y + k / 3 - 1) + oy;
        const float pxx = (float)(xx + k % 3 - 1) + ox;
        const float fy = floorf(py), fx = floorf(pxx);
        const float wy = py - fy,  wx = pxx - fx;
        const int iy0 = (int)fy, ix0 = (int)fx;
        const int iy1 = iy0 + 1, ix1 = ix0 + 1;
        const bool y0v = (iy0 >= 0) && (iy0 < H);
        const bool y1v = (iy1 >= 0) && (iy1 < H);
        const bool x0v = (ix0 >= 0) && (ix0 < W);
        const bool x1v = (ix1 >= 0) && (ix1 < W);
        const int y0c = min(max(iy0, 0), H - 1), y1c = min(max(iy1, 0), H - 1);
        const int x0c = min(max(ix0, 0), W - 1), x1c = min(max(ix1, 0), W - 1);
        int4 bi;
        bi.x = y0c * W + x0c; bi.y = y0c * W + x1c;
        bi.z = y1c * W + x0c; bi.w = y1c * W + x1c;
        float4 wv;
        wv.x = (y0v && x0v) ? (1.f - wy) * (1.f - wx) * m : 0.f;
        wv.y = (y0v && x1v) ? (1.f - wy) * wx * m         : 0.f;
        wv.z = (y1v && x0v) ? wy * (1.f - wx) * m         : 0.f;
        wv.w = (y1v && x1v) ? wy * wx * m                 : 0.f;
        sIdx4[k * 64 + px] = bi;
        sW4  [k * 64 + px] = wv;
    }
    __syncthreads();

    const int ocg = wid & 1;
    const int pxg = wid >> 1;
    float acc[2][2][4];
#pragma unroll
    for (int mt = 0; mt < 2; mt++)
#pragma unroll
        for (int nt = 0; nt < 2; nt++)
#pragma unroll
            for (int c = 0; c < 4; c++) acc[mt][nt][c] = 0.f;

    const __half* xbt = xt + (size_t)b * HW * 64;
    const int gpx = t & 63;                          // gather px
    const int gcg = t >> 6;                          // gather 16-ch group (= ks)

    for (int ch = 0; ch < 9; ch++) {
        if (ch) __syncthreads();
        {
            const uint4* srcw = (const uint4*)((const char*)Ad + (size_t)ch * 18432);
            uint4* dst = (uint4*)(smem + DA_OFF);
            for (int i = t; i < 1152; i += 256) dst[i] = srcw[i];
        }
        // gather: channel-last vectorized; write fragment-order hi/lo blocks
        {
            const int4  bi = sIdx4[ch * 64 + gpx];
            const float4 wv = sW4 [ch * 64 + gpx];
            const uint4* p0 = (const uint4*)(xbt + (size_t)bi.x * 64 + gcg * 16);
            const uint4* p1 = (const uint4*)(xbt + (size_t)bi.y * 64 + gcg * 16);
            const uint4* p2 = (const uint4*)(xbt + (size_t)bi.z * 64 + gcg * 16);
            const uint4* p3 = (const uint4*)(xbt + (size_t)bi.w * 64 + gcg * 16);
            __align__(16) __half2 v0[8], v1[8], v2[8], v3[8];
            *(uint4*)(v0)     = __ldg(p0);  *(uint4*)(v0 + 4) = __ldg(p0 + 1);
            *(uint4*)(v1)     = __ldg(p1);  *(uint4*)(v1 + 4) = __ldg(p1 + 1);
            *(uint4*)(v2)     = __ldg(p2);  *(uint4*)(v2 + 4) = __ldg(p2 + 1);
            *(uint4*)(v3)     = __ldg(p3);  *(uint4*)(v3 + 4) = __ldg(p3 + 1);
            char* bp = smem + DB_OFF + gpx * 320 + gcg * 64;
#pragma unroll
            for (int it = 0; it < 8; it++) {         // c-pair (2*it, 2*it+1) within ks
                const float2 f0 = __half22float2(v0[it]);
                const float2 f1 = __half22float2(v1[it]);
                const float2 f2 = __half22float2(v2[it]);
                const float2 f3 = __half22float2(v3[it]);
                float s0 = wv.x * f0.x;
                s0 = fmaf(wv.y, f1.x, s0);
                s0 = fmaf(wv.z, f2.x, s0);
                s0 = fmaf(wv.w, f3.x, s0);
                float s1 = wv.x * f0.y;
                s1 = fmaf(wv.y, f1.y, s1);
                s1 = fmaf(wv.z, f2.y, s1);
                s1 = fmaf(wv.w, f3.y, s1);
                const __nv_bfloat16 h0 = __float2bfloat16(s0);
                const __nv_bfloat16 h1 = __float2bfloat16(s1);
                __nv_bfloat162 hp; hp.x = h0; hp.y = h1;
                __nv_bfloat162 lp;
                lp.x = __float2bfloat16(s0 - __bfloat162float(h0));
                lp.y = __float2bfloat16(s1 - __bfloat162float(h1));
                const int p    = it & 3;             // block index
                const int half = it >> 2;            // k<8 or k>=8 slot
                *(__nv_bfloat162*)(bp + p * 16 + half * 4)     = hp;
                *(__nv_bfloat162*)(bp + p * 16 + half * 4 + 8) = lp;
            }
        }
        __syncthreads();

#pragma unroll 1
        for (int ks = 0; ks < 4; ks++) {
            unsigned Ah[2][4], Al[2][4];
#pragma unroll
            for (int mt = 0; mt < 2; mt++) {
                const unsigned ao = DA_OFF +
                    ((ocg * 32 + mt * 16 + (lane & 15)) * 72 + ks * 16 + (lane >> 4) * 8) * 2;
                ldsm4(Ah[mt], sbase + ao);
                ldsm4(Al[mt], sbase + ao + 9216);
            }
#pragma unroll
            for (int nt = 0; nt < 2; nt++) {
                const int pxn = pxg * 16 + nt * 8 + (lane >> 2);
                const uint4 q = *(const uint4*)(smem + DB_OFF + pxn * 320 + ks * 64 + (lane & 3) * 16);
#pragma unroll
                for (int mt = 0; mt < 2; mt++) {
                    mma16816(acc[mt][nt], Ah[mt], q.x, q.y);
                    mma16816(acc[mt][nt], Ah[mt], q.z, q.w);
                    mma16816(acc[mt][nt], Al[mt], q.x, q.y);
                }
            }
        }
    }

#pragma unroll
    for (int mt = 0; mt < 2; mt++) {
        const int ocA = ocg * 32 + mt * 16 + (lane >> 2);
        const int ocB = ocA + 8;
        const float bA = __ldg(bias + ocA);
        const float bB = __ldg(bias + ocB);
#pragma unroll
        for (int nt = 0; nt < 2; nt++) {
            const int px = x0 + pxg * 16 + nt * 8 + 2 * (lane & 3);
            const float* c = acc[mt][nt];
            float2 vA, vB;
            vA.x = lrelu(c[0] + bA); vA.y = lrelu(c[1] + bA);
            vB.x = lrelu(c[2] + bB); vB.y = lrelu(c[3] + bB);
            *(float2*)(out + ((size_t)b * NF + ocA) * HW + y * W + px) = vA;
            *(float2*)(out + ((size_t)b * NF + ocB) * HW + y * W + px) = vB;
        }
    }
}

// ---------------------------------------------------------------------------
extern "C" void kernel_launch(void* const* d_in, const int* in_sizes, int n_in,
                              void* d_out, int out_size)
{
    const float* nbr   = (const float*)d_in[0];
    const float* ref   = (const float*)d_in[1];
    const float* w1    = (const float*)d_in[2];
    const float* b1    = (const float*)d_in[3];
    const float* w2    = (const float*)d_in[4];
    const float* b2    = (const float*)d_in[5];
    const float* w3    = (const float*)d_in[6];
    const float* b3    = (const float*)d_in[7];
    const float* w_off = (const float*)d_in[8];
    const float* b_off = (const float*)d_in[9];
    const float* w_dcn = (const float*)d_in[10];
    const float* b_dcn = (const float*)d_in[11];

    float* out  = (float*)d_out;
    float* feat = out;                                   // [B,64,H,W]
    float* offs = out + (size_t)BN * NF * HW;            // [B,18,H,W]
    float* msk  = offs + (size_t)BN * 18 * HW;           // [B, 9,H,W]

    unsigned *bufA, *bufB;
    __half* xt;
    __nv_bfloat16 *A1, *A2, *A3, *Ao, *Ad;
    cudaGetSymbolAddress((void**)&bufA, g_bufA);
    cudaGetSymbolAddress((void**)&bufB, g_bufB);
    cudaGetSymbolAddress((void**)&xt,   g_xt);
    cudaGetSymbolAddress((void**)&A1,   g_A1);
    cudaGetSymbolAddress((void**)&A2,   g_A2);
    cudaGetSymbolAddress((void**)&A3,   g_A3);
    cudaGetSymbolAddress((void**)&Ao,   g_Ao);
    cudaGetSymbolAddress((void**)&Ad,   g_Ad);

    prep_weights<<<1584, 256>>>(w1, A1, w2, A2, w3, A3, w_off, Ao, w_dcn, Ad);
    prep_xt<<<dim3(64, BN), 256>>>(nbr, xt);

    cudaFuncSetAttribute(conv_mma_kernel<2, false>,
                         cudaFuncAttributeMaxDynamicSharedMemorySize, CSM_SIZE);
    cudaFuncSetAttribute(conv_mma_kernel<1, true>,
                         cudaFuncAttributeMaxDynamicSharedMemorySize, CSM_SIZE);
    cudaFuncSetAttribute(conv_off_mma_kernel,
                         cudaFuncAttributeMaxDynamicSharedMemorySize, OSM_SIZE);
    cudaFuncSetAttribute(dcn_mma_kernel,
                         cudaFuncAttributeMaxDynamicSharedMemorySize, DSM_SIZE);

    conv_mma_kernel<2, false><<<dim3(2, 64, 4), 256, CSM_SIZE>>>(nbr, ref, nullptr, A1, b1, bufA);
    conv_mma_kernel<1, true ><<<dim3(2, 64, 4), 256, CSM_SIZE>>>(nullptr, nullptr, bufA, A2, b2, bufB);
    conv_mma_kernel<1, true ><<<dim3(2, 64, 4), 256, CSM_SIZE>>>(nullptr, nullptr, bufB, A3, b3, bufA);
    conv_off_mma_kernel<<<dim3(2, 64, 4), 256, OSM_SIZE>>>(bufA, Ao, b_off, offs, msk);

    dcn_mma_kernel<<<dim3(2, 128, 4), 256, DSM_SIZE>>>(xt, offs, msk, Ad, b_dcn, feat);
}